// round 17
// baseline (speedup 1.0000x reference)
#include <cuda_runtime.h>
#include <cuda_bf16.h>
#include <cstdint>

#define BCH   10
#define HH    320
#define WW    1024
#define PTS   500
#define DENSE 2000
#define KMEAN 10
#define NPTS  (BCH * PTS)
#define CHUNKS 500            // int4 chunks per point

#define PPW  4                // points validated per warp
#define PPB  16               // points per block (4 warps)
#define NBLK ((NPTS + PPB - 1) / PPB)   // 313

// Window: by in [-7,7] (15 rows), bx in [-11,11] (23 cols), padded to 32 cols.
#define WROWS 15
#define WCOLS 23
#define HSLOTS (WROWS * 32)   // 480
#define FULLM 0xFFFFFFFFu

// CTA = 4 warps owns 16 points. Phase A: each warp validates 4 points
// (sequential, pipelined loads), compacts valid ones into a smem queue.
// Phase B: warps pull queue entries round-robin -> heavy work balanced
// 4-per-warp-group instead of Poisson-scattered across 5000 CTAs.
__global__ __launch_bounds__(128, 8)
void rsbsp_kernel(const float* __restrict__ disp,
                  const float* __restrict__ fore,
                  const int*   __restrict__ cxs,
                  const int*   __restrict__ cys,
                  const int*   __restrict__ bxs,
                  const int*   __restrict__ bys,
                  float*       __restrict__ out)
{
    __shared__ int hist[4][HSLOTS];
    __shared__ int s_queue[PPB];
    __shared__ int s_cnt;

    const int w    = threadIdx.x >> 5;
    const int lane = threadIdx.x & 31;

    if (threadIdx.x == 0) s_cnt = 0;
    __syncthreads();

    // ---- Phase A: validate this warp's 4 points ---------------------------
    const int p0 = blockIdx.x * PPB + w * PPW;
    int cxv = 0, cyv = 0;
    if (lane < PPW && p0 + lane < NPTS) {
        cxv = cxs[p0 + lane];
        cyv = cys[p0 + lane];
    }

    const int r5 = lane / 5;
    const int c5 = lane - r5 * 5;

    #pragma unroll
    for (int r = 0; r < PPW; r++) {
        const int n = p0 + r;
        if (n >= NPTS) break;                       // warp-uniform (p0 uniform)
        const int cx = __shfl_sync(FULLM, cxv, r);
        const int cy = __shfl_sync(FULLM, cyv, r);
        const int chan = n / PTS;
        const float* dch = disp + (size_t)chan * (HH * WW);
        const float* fch = fore + (size_t)chan * (HH * WW);
        const int    base = (cy << 10) + cx;        // WW == 1024

        // maxpool3x3(|sobel_x(forepred)|)(cy,cx) > 3.1 && disp(cy,cx) > 0.007
        // Centers >= 11 px from all borders (zeroArea never reached).
        // Lane l<25 loads the 5x5 forepred window (one LDG instruction).
        float wv = 0.0f;
        if (lane < 25)
            wv = fch[(size_t)(cy + r5 - 2) * WW + (cx + c5 - 2)];
        float dC = 0.0f;
        if (lane == 25) dC = dch[base];
        dC = __shfl_sync(FULLM, dC, 25);

        const float wup = __shfl_sync(FULLM, wv, (lane + 27) & 31);  // lane-5
        const float wdn = __shfl_sync(FULLM, wv, (lane + 5)  & 31);  // lane+5
        const float cs  = wup + 2.0f * wv + wdn;
        const float csl = __shfl_sync(FULLM, cs, (lane + 31) & 31);  // lane-1
        const float csr = __shfl_sync(FULLM, cs, (lane + 1)  & 31);  // lane+1
        float gg = 0.0f;
        if (r5 >= 1 && r5 <= 3 && c5 >= 1 && c5 <= 3)
            gg = fabsf(csr - csl);
        const float g =
            __uint_as_float(__reduce_max_sync(FULLM, __float_as_uint(gg)));

        if ((g > 3.1f) && (dC > 0.007f)) {
            if (lane == 0) {
                const int pos = atomicAdd(&s_cnt, 1);
                s_queue[pos] = n;
            }
        } else if (lane == 0) {
            out[2 * n] = 0.0f; out[2 * n + 1] = 0.0f;
        }
    }
    __syncthreads();

    // ---- Phase B: warps pull compacted heavy points round-robin -----------
    const int cnt = s_cnt;
    int* h = hist[w];

    for (int j = w; j < cnt; j += 4) {
        const int n    = s_queue[j];
        const int chan = n / PTS;
        const int cx   = cxs[n];
        const int cy   = cys[n];
        const float* dch  = disp + (size_t)chan * (HH * WW);
        const int    base = (cy << 10) + cx;

        // zero private histogram
        #pragma unroll
        for (int r = 0; r < WROWS; r++) h[lane + (r << 5)] = 0;
        __syncwarp();

        // histogram the 2000 samples over the 15x23 window
        const int4* bx4p = (const int4*)(bxs + (size_t)n * DENSE);
        const int4* by4p = (const int4*)(bys + (size_t)n * DENSE);
        #pragma unroll 8
        for (int k = 0; k < 16; k++) {
            const int  c     = lane + (k << 5);
            const bool valid = (k < 15) || (c < CHUNKS);
            if (valid) {
                const int4 b4 = bx4p[c];
                const int4 y4 = by4p[c];
                // slot = (y+7)*32 + (x+11) = y*32 + x + 235
                atomicAdd(&h[(y4.x << 5) + b4.x + 235], 1);
                atomicAdd(&h[(y4.y << 5) + b4.y + 235], 1);
                atomicAdd(&h[(y4.z << 5) + b4.z + 235], 1);
                atomicAdd(&h[(y4.w << 5) + b4.w + 235], 1);
            }
        }
        __syncwarp();

        // weighted stats over the 15x23 window
        float val [WROWS];
        float prod[WROWS];
        float cntf[WROWS];
        float mx = -1e30f, mn = 1e30f, stot = 0.0f;
        #pragma unroll
        for (int r = 0; r < WROWS; r++) {
            const int   c2  = h[lane + (r << 5)];
            const float v   = (lane < WCOLS)
                            ? dch[base + (r - 7) * WW + (lane - 11)]
                            : 0.0f;
            const float cf  = (float)c2;
            val[r]  = v;
            cntf[r] = cf;
            prod[r] = v * cf;
            stot   += prod[r];
            if (c2 > 0) { mx = fmaxf(mx, v); mn = fminf(mn, v); }
        }
        #pragma unroll
        for (int o = 16; o; o >>= 1) {
            mx   = fmaxf(mx, __shfl_xor_sync(FULLM, mx, o));
            mn   = fminf(mn, __shfl_xor_sync(FULLM, mn, o));
            stot +=          __shfl_xor_sync(FULLM, stot, o);
        }

        // weighted 2-cluster 1-D k-means over <=345 unique values.
        // kL > kS => |s-kL|<=|s-kS| <=> s >= (kL+kS)/2 (midpoint tie -> large,
        // matching dl<=ds). Threshold acts on val only => weighted sums equal
        // per-sample sums exactly. Bitwise fixed point => exact early exit.
        float kL = mx, kS = mn;
        float lastCnt = 0.0f;
        #pragma unroll 1
        for (int it = 0; it < KMEAN; it++) {
            const float mid = 0.5f * (kL + kS);
            float sumL = 0.0f, cntL = 0.0f;
            #pragma unroll
            for (int r = 0; r < WROWS; r++) {
                if (val[r] >= mid) { sumL += prod[r]; cntL += cntf[r]; }
            }
            #pragma unroll
            for (int o = 16; o; o >>= 1) {
                sumL += __shfl_xor_sync(FULLM, sumL, o);
                cntL += __shfl_xor_sync(FULLM, cntL, o);
            }
            const float nkL = __fdividef(sumL, cntL);
            const float nkS = __fdividef(stot - sumL, (float)DENSE - cntL);
            lastCnt = cntL;
            const bool conv = (nkL == kL) && (nkS == kS);
            kL = nkL; kS = nkS;
            if (conv) break;
        }

        const bool keep = ((kL - kS) > 0.005f) && (lastCnt > 5.0f);
        if (lane == 0) {
            const float kf = keep ? 1.0f : 0.0f;
            out[2 * n]     = kL * kf;
            out[2 * n + 1] = kS * kf;
        }
    }
}

extern "C" void kernel_launch(void* const* d_in, const int* in_sizes, int n_in,
                              void* d_out, int out_size)
{
    const float* disp = (const float*)d_in[0];
    const float* fore = (const float*)d_in[1];
    const int*   cxs  = (const int*)  d_in[2];
    const int*   cys  = (const int*)  d_in[3];
    const int*   bxs  = (const int*)  d_in[4];
    const int*   bys  = (const int*)  d_in[5];
    float*       out  = (float*)d_out;

    rsbsp_kernel<<<NBLK, 128>>>(disp, fore, cxs, cys, bxs, bys, out);
}